// round 12
// baseline (speedup 1.0000x reference)
#include <cuda_runtime.h>

#define MAXN 4096
#define IMG_W 128
#define IMG_H 128
#define TILE 8
#define TILES_X 16
#define GRID4 256
#define BLK4 512
#define FXc 300.0f
#define FYc 300.0f
#define LOG2E 1.4426950408889634f

// ---- scratch (allocation-free per harness rules) ----
__device__ int    g_rank[MAXN];   // zeroed at end of each launch (and statically)
__device__ float4 g_a[MAXN];      // (u, v, A2, B2)       [geom]
__device__ float4 g_d[MAXN];      // (Cc2, op_eff, r2, -) [geom]
__device__ float4 g_col[MAXN];    // (r, g, b, -)         [color, per-channel writers]
__device__ float4 s_a[MAXN];      // sorted (u, v, A2, B2)
__device__ float4 s_b[MAXN];      // sorted (Cc2, op, colR, colG)
__device__ float2 s_c[MAXN];      // sorted (colB, r2)
__device__ unsigned int g_leaf[8];   // monotonic two-level barrier
__device__ unsigned int g_root;

__device__ __constant__ float C0 = 0.28209479177387814f;
__device__ __constant__ float C1 = 0.4886025119029199f;
__device__ __constant__ float C2_[5] = {1.0925484305920792f, -1.0925484305920792f,
                                        0.31539156525252005f, -1.0925484305920792f,
                                        0.5462742152960396f};
__device__ __constant__ float C3_[7] = {-0.5900435899266435f, 2.890611442640554f,
                                        -0.4570457994644658f, 0.3731763325901154f,
                                        -0.4570457994644658f, 1.445305721320277f,
                                        -0.5900435899266435f};

// Two-level monotonic barrier (replay-safe; counters only grow, +GRID4/launch).
// 256 blocks: 8 leaves × 32 arrivals; 32nd arrival of a leaf round bumps root.
__device__ __forceinline__ void gbar() {
    __syncthreads();
    __threadfence();
    if (threadIdx.x == 0) {
        int leaf = blockIdx.x & 7;
        unsigned int old = atomicAdd(&g_leaf[leaf], 1u);
        if ((old & 31u) == 31u) atomicAdd(&g_root, 1u);
        unsigned int target = ((old >> 5) + 1u) * 8u;
        while (*((volatile unsigned int*)&g_root) < target) { __nanosleep(32); }
        __threadfence();
    }
    __syncthreads();
}

__global__ void __launch_bounds__(BLK4, 2) fused_kernel(
        const float* __restrict__ pw,
        const float* __restrict__ lowsh,
        const float* __restrict__ highsh,
        const float* __restrict__ rawop,
        const float* __restrict__ sraw,
        const float* __restrict__ rraw,
        const float* __restrict__ Rcw,
        const float* __restrict__ tcw,
        float* __restrict__ out,
        int n) {
    int t   = threadIdx.x;
    int blk = blockIdx.x;
    int gid = blk * BLK4 + t;

    // ------------- Phase A: geom || color || rank on disjoint threads -------------
    if (gid < n) {
        // ---- geom ----
        int i = gid;

        float R00=Rcw[0],R01=Rcw[1],R02=Rcw[2];
        float R10=Rcw[3],R11=Rcw[4],R12=Rcw[5];
        float R20=Rcw[6],R21=Rcw[7],R22=Rcw[8];
        float t0=tcw[0], t1=tcw[1], t2=tcw[2];

        float px = pw[i*3+0], py = pw[i*3+1], pz = pw[i*3+2];

        float pc0 = R00*px + R01*py + R02*pz + t0;
        float pc1 = R10*px + R11*py + R12*pz + t1;
        float pc2 = fmaf(R22, pz, fmaf(R21, py, fmaf(R20, px, t2)));  // matches rank's z
        float invz = 1.0f / pc2;
        float u = FXc * pc0 * invz + 0.5f * IMG_W;
        float v = FYc * pc1 * invz + 0.5f * IMG_H;

        float op = 1.0f / (1.0f + __expf(-rawop[i]));

        float s0 = __expf(sraw[i*3+0]);
        float s1 = __expf(sraw[i*3+1]);
        float s2 = __expf(sraw[i*3+2]);

        float qw = rraw[i*4+0], qx = rraw[i*4+1], qy = rraw[i*4+2], qz = rraw[i*4+3];
        float qn = rsqrtf(qw*qw + qx*qx + qy*qy + qz*qz);
        qw *= qn; qx *= qn; qy *= qn; qz *= qn;

        float Rg00 = 1.0f - 2.0f*(qy*qy + qz*qz);
        float Rg01 = 2.0f*(qx*qy - qw*qz);
        float Rg02 = 2.0f*(qx*qz + qw*qy);
        float Rg10 = 2.0f*(qx*qy + qw*qz);
        float Rg11 = 1.0f - 2.0f*(qx*qx + qz*qz);
        float Rg12 = 2.0f*(qy*qz - qw*qx);
        float Rg20 = 2.0f*(qx*qz - qw*qy);
        float Rg21 = 2.0f*(qy*qz + qw*qx);
        float Rg22 = 1.0f - 2.0f*(qx*qx + qy*qy);

        float M00 = Rg00*s0, M01 = Rg01*s1, M02 = Rg02*s2;
        float M10 = Rg10*s0, M11 = Rg11*s1, M12 = Rg12*s2;
        float M20 = Rg20*s0, M21 = Rg21*s1, M22 = Rg22*s2;

        float j00 = FXc*invz, j02 = -FXc*pc0*invz*invz;
        float j11 = FYc*invz, j12 = -FYc*pc1*invz*invz;
        float T00 = j00*R00 + j02*R20;
        float T01 = j00*R01 + j02*R21;
        float T02 = j00*R02 + j02*R22;
        float T10 = j11*R10 + j12*R20;
        float T11 = j11*R11 + j12*R21;
        float T12 = j11*R12 + j12*R22;

        float V00 = T00*M00 + T01*M10 + T02*M20;
        float V01 = T00*M01 + T01*M11 + T02*M21;
        float V02 = T00*M02 + T01*M12 + T02*M22;
        float V10 = T10*M00 + T11*M10 + T12*M20;
        float V11 = T10*M01 + T11*M11 + T12*M21;
        float V12 = T10*M02 + T11*M12 + T12*M22;

        float a  = V00*V00 + V01*V01 + V02*V02 + 0.3f;
        float b  = V00*V10 + V01*V11 + V02*V12;
        float cc = V10*V10 + V11*V11 + V12*V12 + 0.3f;
        float det = a*cc - b*b;
        float idet = 1.0f / det;
        float ia =  cc * idet;
        float ib = -b  * idet;
        float ic =  a  * idet;

        float op_eff = (pc2 > 0.2f) ? op : 0.0f;

        float A2  = -0.5f * ia * LOG2E;
        float B2  = -ib * LOG2E;
        float Cc2 = -0.5f * ic * LOG2E;

        float mid  = 0.5f * (a + cc);
        float disc = sqrtf(0.25f * (a - cc) * (a - cc) + b * b);
        float lmax = mid + disc;
        float t255 = 255.0f * op_eff;
        float r2 = (t255 > 1.0f) ? 2.0f * __logf(t255) * lmax * 1.0002f : -1.0f;

        g_a[i] = make_float4(u, v, A2, B2);
        g_d[i] = make_float4(Cc2, op_eff, r2, 0.0f);
    } else if (gid < 4 * n) {
        // ---- color: SH -> rgb, 3 threads per gaussian (one channel each) ----
        int cid = gid - n;
        int i  = cid / 3;
        int ch = cid - 3 * i;

        float R00=Rcw[0],R01=Rcw[1],R02=Rcw[2];
        float R10=Rcw[3],R11=Rcw[4],R12=Rcw[5];
        float R20=Rcw[6],R21=Rcw[7],R22=Rcw[8];
        float t0=tcw[0], t1=tcw[1], t2=tcw[2];

        float px = pw[i*3+0], py = pw[i*3+1], pz = pw[i*3+2];

        float dx0 = px + (R00*t0 + R10*t1 + R20*t2);
        float dy0 = py + (R01*t0 + R11*t1 + R21*t2);
        float dz0 = pz + (R02*t0 + R12*t1 + R22*t2);
        float dn = rsqrtf(dx0*dx0 + dy0*dy0 + dz0*dz0);
        float x = dx0*dn, y = dy0*dn, z = dz0*dn;

        float xx = x*x, yy = y*y, zz = z*z;
        float xy = x*y, yz = y*z, xz = x*z;

        const float* hs = highsh + i*45 + ch;
        float res = C0 * lowsh[i*3+ch];
        res += (-C1*y) * hs[0*3] + (C1*z) * hs[1*3] + (-C1*x) * hs[2*3];
        res += (C2_[0]*xy) * hs[3*3] + (C2_[1]*yz) * hs[4*3]
             + (C2_[2]*(2.0f*zz - xx - yy)) * hs[5*3]
             + (C2_[3]*xz) * hs[6*3] + (C2_[4]*(xx - yy)) * hs[7*3];
        res += (C3_[0]*y*(3.0f*xx - yy)) * hs[8*3]
             + (C3_[1]*xy*z) * hs[9*3]
             + (C3_[2]*y*(4.0f*zz - xx - yy)) * hs[10*3]
             + (C3_[3]*z*(2.0f*zz - 3.0f*xx - 3.0f*yy)) * hs[11*3]
             + (C3_[4]*x*(4.0f*zz - xx - yy)) * hs[12*3]
             + (C3_[5]*z*(xx - yy)) * hs[13*3]
             + (C3_[6]*x*(xx - 3.0f*yy)) * hs[14*3];
        ((float*)&g_col[i])[ch] = fmaxf(res + 0.5f, 0.0f);
    } else {
        // ---- distributed stable rank, z computed on the fly (exact fmaf chain) ----
        int total = GRID4 * BLK4;
        int NS = total / n - 4;
        if (NS < 1) NS = 1;
        int rid = gid - 4 * n;
        if (rid < n * NS) {
            int i     = rid % n;
            int slice = rid / n;
            int JL = (n + NS - 1) / NS;
            int j0 = slice * JL;
            if (j0 < n) {
                int j1 = min(n, j0 + JL);
                float R20=Rcw[6], R21=Rcw[7], R22=Rcw[8], t2=tcw[2];
                float zi = fmaf(R22, pw[i*3+2], fmaf(R21, pw[i*3+1], fmaf(R20, pw[i*3+0], t2)));
                int r = 0;
                for (int j = j0; j < j1; j++) {
                    float zj = fmaf(R22, pw[j*3+2], fmaf(R21, pw[j*3+1], fmaf(R20, pw[j*3+0], t2)));
                    r += (zj < zi) || (zj == zi && j < i);
                }
                if (r) atomicAdd(&g_rank[i], r);
            }
        }
    }

    gbar();

    // ---------------- Phase B: scatter into depth order ----------------
    if (gid < n) {
        int r = g_rank[gid];
        float4 d = g_d[gid];
        float4 c = g_col[gid];
        s_a[r] = g_a[gid];
        s_b[r] = make_float4(d.x, d.y, c.x, c.y);
        s_c[r] = make_float2(c.z, d.z);   // (colB, r2)
    }

    gbar();

    // ------ Phase C: cull (order-preserving) + warp split-K blend + compose ------
    {
        __shared__ unsigned short slist[MAXN];
        __shared__ int wcnt[16];
        __shared__ float4 ca[16][32], cb[16][32];
        __shared__ float  ccb[16][32];
        __shared__ float4 part[8][64];

        // re-zero ranks for the NEXT launch (scatter above already consumed them)
        if (gid < n) g_rank[gid] = 0;

        int tlx = blk & (TILES_X - 1);
        int tly = blk >> 4;

        float xlo = tlx * TILE + 0.5f, xhi = tlx * TILE + (TILE - 0.5f);
        float ylo = tly * TILE + 0.5f, yhi = tly * TILE + (TILE - 0.5f);

        int wid = t >> 5, lid = t & 31;
        unsigned lmask = (1u << lid) - 1u;

        // order-preserving cull over the depth-sorted arrays (16 warps)
        int cnt = 0;
        for (int c = 0; c < n; c += BLK4) {
            int i = c + t;
            int pred = 0;
            if (i < n) {
                float4 A = s_a[i];
                float r2 = s_c[i].y;
                float cu = fminf(fmaxf(A.x, xlo), xhi);
                float cv = fminf(fmaxf(A.y, ylo), yhi);
                float ddx = A.x - cu, ddy = A.y - cv;
                pred = (ddx * ddx + ddy * ddy <= r2) ? 1 : 0;
            }
            unsigned m = __ballot_sync(0xffffffffu, pred);
            if (lid == 0) wcnt[wid] = __popc(m);
            __syncthreads();
            int off = cnt + __popc(m & lmask);
            int tot = 0;
            #pragma unroll
            for (int w = 0; w < 16; w++) {
                int c16 = wcnt[w];
                if (w < wid) off += c16;
                tot += c16;
            }
            if (pred) slist[off] = (unsigned short)i;
            __syncthreads();
            cnt += tot;
        }

        // warp split-K: warp w = (segment q = w>>1, pixel-half h = w&1).
        // Each warp autonomously stages its own chunk and blends its 32 pixels.
        int q = wid >> 1;
        int h = wid & 1;
        int pix = h * 32 + lid;                 // 0..63 within 8x8 tile
        float pxf = tlx * TILE + (pix & 7) + 0.5f;
        float pyf = tly * TILE + (pix >> 3) + 0.5f;

        int L8 = (cnt + 7) >> 3;
        int qbeg = q * L8;
        int qend = min(cnt, qbeg + L8);

        float T = 1.0f, cr = 0.0f, cg = 0.0f, cbl = 0.0f;

        for (int base = 0; base < L8; base += 32) {
            if (__all_sync(0xffffffffu, T < 1e-5f)) break;
            int src = qbeg + base + lid;
            if (src < qend) {
                int idx = slist[src];
                ca[wid][lid]  = s_a[idx];
                cb[wid][lid]  = s_b[idx];
                ccb[wid][lid] = s_c[idx].x;
            }
            __syncwarp();
            int m = min(32, qend - (qbeg + base));
            #pragma unroll 4
            for (int k = 0; k < m; k++) {
                float4 A = ca[wid][k];
                float4 B = cb[wid][k];
                float dx = A.x - pxf;
                float dy = A.y - pyf;
                float pp = A.z * dx * dx;
                pp = fmaf(B.x, dy * dy, pp);
                pp = fmaf(A.w, dx * dy, pp);
                pp = fminf(pp, 0.0f);
                float gw;
                asm("ex2.approx.f32 %0, %1;" : "=f"(gw) : "f"(pp));
                float alpha = fminf(0.99f, B.y * gw);
                alpha = (alpha >= (1.0f / 255.0f)) ? alpha : 0.0f;
                float w = T * alpha;
                cr  = fmaf(w, B.z, cr);
                cg  = fmaf(w, B.w, cg);
                cbl = fmaf(w, ccb[wid][k], cbl);
                T = fmaf(-alpha, T, T);
            }
            __syncwarp();
        }

        part[q][pix] = make_float4(cr, cg, cbl, T);
        __syncthreads();

        // compose 8 segments front-to-back (threads 0..63)
        if (t < 64) {
            float Tc = 1.0f, rr = 0.0f, gg = 0.0f, bb = 0.0f;
            #pragma unroll
            for (int s = 0; s < 8; s++) {
                float4 P = part[s][t];
                rr = fmaf(Tc, P.x, rr);
                gg = fmaf(Tc, P.y, gg);
                bb = fmaf(Tc, P.z, bb);
                Tc *= P.w;
            }
            int pxi = tlx * TILE + (t & 7);
            int pyi = tly * TILE + (t >> 3);
            int o = (pyi * IMG_W + pxi) * 3;
            out[o + 0] = rr;
            out[o + 1] = gg;
            out[o + 2] = bb;
        }
    }
}

extern "C" void kernel_launch(void* const* d_in, const int* in_sizes, int n_in,
                              void* d_out, int out_size) {
    const float* pw     = (const float*)d_in[0];
    const float* lowsh  = (const float*)d_in[1];
    const float* highsh = (const float*)d_in[2];
    const float* rawop  = (const float*)d_in[3];
    const float* sraw   = (const float*)d_in[4];
    const float* rraw   = (const float*)d_in[5];
    const float* Rcw    = (const float*)d_in[6];
    const float* tcw    = (const float*)d_in[7];
    int n = in_sizes[0] / 3;

    fused_kernel<<<GRID4, BLK4>>>(pw, lowsh, highsh, rawop, sraw, rraw, Rcw, tcw,
                                  (float*)d_out, n);
}

// round 14
// speedup vs baseline: 1.0233x; 1.0233x over previous
#include <cuda_runtime.h>

#define MAXN 4096
#define IMG_W 128
#define IMG_H 128
#define TILE 8
#define TILES_X 16
#define GRID4 256
#define BLK4 512
#define FXc 300.0f
#define FYc 300.0f
#define LOG2E 1.4426950408889634f

// ---- scratch (allocation-free per harness rules) ----
__device__ int    g_rank[MAXN];   // zeroed at end of each launch (and statically)
__device__ float4 g_a[MAXN];      // (u, v, A2, B2)        [geom]
__device__ float4 g_d[MAXN];      // (Cc2, op_eff, thr, -) [geom]
__device__ float2 g_k[MAXN];      // (kX, kY)              [geom]
__device__ float4 g_col[MAXN];    // (r, g, b, -)          [color, per-channel writers]
__device__ float4 s_a[MAXN];      // sorted (u, v, A2, B2)
__device__ float4 s_b[MAXN];      // sorted (Cc2, op, colR, colG)
__device__ float4 s_c[MAXN];      // sorted (colB, thr, kX, kY)
__device__ unsigned int g_leaf[8];   // monotonic two-level barrier
__device__ unsigned int g_root;

__device__ __constant__ float C0 = 0.28209479177387814f;
__device__ __constant__ float C1 = 0.4886025119029199f;
__device__ __constant__ float C2_[5] = {1.0925484305920792f, -1.0925484305920792f,
                                        0.31539156525252005f, -1.0925484305920792f,
                                        0.5462742152960396f};
__device__ __constant__ float C3_[7] = {-0.5900435899266435f, 2.890611442640554f,
                                        -0.4570457994644658f, 0.3731763325901154f,
                                        -0.4570457994644658f, 1.445305721320277f,
                                        -0.5900435899266435f};

// Two-level monotonic barrier (replay-safe; counters only grow, +GRID4/launch).
__device__ __forceinline__ void gbar() {
    __syncthreads();
    __threadfence();
    if (threadIdx.x == 0) {
        int leaf = blockIdx.x & 7;
        unsigned int old = atomicAdd(&g_leaf[leaf], 1u);
        if ((old & 31u) == 31u) atomicAdd(&g_root, 1u);
        unsigned int target = ((old >> 5) + 1u) * 8u;
        while (*((volatile unsigned int*)&g_root) < target) { __nanosleep(32); }
        __threadfence();
    }
    __syncthreads();
}

struct PhaseC {
    unsigned short slist[MAXN];
    int    wcnt[16];
    float4 ca[16][32];
    float4 cb[16][32];
    float  ccb[16][32];
    float4 part[8][64];
};
union SmemU {
    float  z[MAXN];   // phase A (rank blocks)
    PhaseC c;         // phase C (all blocks) — separated by gbar
};

__global__ void __launch_bounds__(BLK4, 2) fused_kernel(
        const float* __restrict__ pw,
        const float* __restrict__ lowsh,
        const float* __restrict__ highsh,
        const float* __restrict__ rawop,
        const float* __restrict__ sraw,
        const float* __restrict__ rraw,
        const float* __restrict__ Rcw,
        const float* __restrict__ tcw,
        float* __restrict__ out,
        int n) {
    __shared__ SmemU sm;

    int t   = threadIdx.x;
    int blk = blockIdx.x;
    int gid = blk * BLK4 + t;

    int rankStart = (4 * n + BLK4 - 1) / BLK4;   // first all-rank block

    // ------------- Phase A: geom || color || rank on disjoint blocks -------------
    if (blk >= rankStart) {
        // ---- rank block: build z in smem, then compare slice from smem ----
        float R20=Rcw[6], R21=Rcw[7], R22=Rcw[8], t2=tcw[2];
        for (int j = t; j < n; j += BLK4)
            sm.z[j] = fmaf(R22, pw[j*3+2], fmaf(R21, pw[j*3+1], fmaf(R20, pw[j*3+0], t2)));
        __syncthreads();

        int total = GRID4 * BLK4;
        int NS = total / n - 4;
        if (NS < 1) NS = 1;
        int rid = (blk - rankStart) * BLK4 + t;
        if (rid < n * NS) {
            int i     = rid % n;
            int slice = rid / n;
            int JL = (n + NS - 1) / NS;
            int j0 = slice * JL;
            if (j0 < n) {
                int j1 = min(n, j0 + JL);
                float zi = sm.z[i];
                int r = 0;
                for (int j = j0; j < j1; j++) {
                    float zj = sm.z[j];
                    r += (zj < zi) || (zj == zi && j < i);
                }
                if (r) atomicAdd(&g_rank[i], r);
            }
        }
    } else if (gid < n) {
        // ---- geom ----
        int i = gid;

        float R00=Rcw[0],R01=Rcw[1],R02=Rcw[2];
        float R10=Rcw[3],R11=Rcw[4],R12=Rcw[5];
        float R20=Rcw[6],R21=Rcw[7],R22=Rcw[8];
        float t0=tcw[0], t1=tcw[1], t2=tcw[2];

        float px = pw[i*3+0], py = pw[i*3+1], pz = pw[i*3+2];

        float pc0 = R00*px + R01*py + R02*pz + t0;
        float pc1 = R10*px + R11*py + R12*pz + t1;
        float pc2 = fmaf(R22, pz, fmaf(R21, py, fmaf(R20, px, t2)));  // matches rank's z
        float invz = 1.0f / pc2;
        float u = FXc * pc0 * invz + 0.5f * IMG_W;
        float v = FYc * pc1 * invz + 0.5f * IMG_H;

        float op = 1.0f / (1.0f + __expf(-rawop[i]));

        float s0 = __expf(sraw[i*3+0]);
        float s1 = __expf(sraw[i*3+1]);
        float s2 = __expf(sraw[i*3+2]);

        float qw = rraw[i*4+0], qx = rraw[i*4+1], qy = rraw[i*4+2], qz = rraw[i*4+3];
        float qn = rsqrtf(qw*qw + qx*qx + qy*qy + qz*qz);
        qw *= qn; qx *= qn; qy *= qn; qz *= qn;

        float Rg00 = 1.0f - 2.0f*(qy*qy + qz*qz);
        float Rg01 = 2.0f*(qx*qy - qw*qz);
        float Rg02 = 2.0f*(qx*qz + qw*qy);
        float Rg10 = 2.0f*(qx*qy + qw*qz);
        float Rg11 = 1.0f - 2.0f*(qx*qx + qz*qz);
        float Rg12 = 2.0f*(qy*qz - qw*qx);
        float Rg20 = 2.0f*(qx*qz - qw*qy);
        float Rg21 = 2.0f*(qy*qz + qw*qx);
        float Rg22 = 1.0f - 2.0f*(qx*qx + qy*qy);

        float M00 = Rg00*s0, M01 = Rg01*s1, M02 = Rg02*s2;
        float M10 = Rg10*s0, M11 = Rg11*s1, M12 = Rg12*s2;
        float M20 = Rg20*s0, M21 = Rg21*s1, M22 = Rg22*s2;

        float j00 = FXc*invz, j02 = -FXc*pc0*invz*invz;
        float j11 = FYc*invz, j12 = -FYc*pc1*invz*invz;
        float T00 = j00*R00 + j02*R20;
        float T01 = j00*R01 + j02*R21;
        float T02 = j00*R02 + j02*R22;
        float T10 = j11*R10 + j12*R20;
        float T11 = j11*R11 + j12*R21;
        float T12 = j11*R12 + j12*R22;

        float V00 = T00*M00 + T01*M10 + T02*M20;
        float V01 = T00*M01 + T01*M11 + T02*M21;
        float V02 = T00*M02 + T01*M12 + T02*M22;
        float V10 = T10*M00 + T11*M10 + T12*M20;
        float V11 = T10*M01 + T11*M11 + T12*M21;
        float V12 = T10*M02 + T11*M12 + T12*M22;

        float a  = V00*V00 + V01*V01 + V02*V02 + 0.3f;
        float b  = V00*V10 + V01*V11 + V02*V12;
        float cc = V10*V10 + V11*V11 + V12*V12 + 0.3f;
        float det = a*cc - b*b;
        float idet = 1.0f / det;
        float ia =  cc * idet;
        float ib = -b  * idet;
        float ic =  a  * idet;

        float op_eff = (pc2 > 0.2f) ? op : 0.0f;

        float A2  = -0.5f * ia * LOG2E;   // < 0
        float B2  = -ib * LOG2E;
        float Cc2 = -0.5f * ic * LOG2E;   // < 0

        // exact-cull constants: keep iff max_box(A2 dx^2 + Cc2 dy^2 + B2 dx dy) >= thr
        float thr = -__log2f(255.0f * op_eff);           // +inf when op_eff == 0
        float kX  = __fdividef(-B2, 2.0f * A2);
        float kY  = __fdividef(-B2, 2.0f * Cc2);

        g_a[i] = make_float4(u, v, A2, B2);
        g_d[i] = make_float4(Cc2, op_eff, thr, 0.0f);
        g_k[i] = make_float2(kX, kY);
    } else if (gid < 4 * n) {
        // ---- color: SH -> rgb, 3 threads per gaussian (one channel each) ----
        int cid = gid - n;
        int i  = cid / 3;
        int ch = cid - 3 * i;

        float R00=Rcw[0],R01=Rcw[1],R02=Rcw[2];
        float R10=Rcw[3],R11=Rcw[4],R12=Rcw[5];
        float R20=Rcw[6],R21=Rcw[7],R22=Rcw[8];
        float t0=tcw[0], t1=tcw[1], t2=tcw[2];

        float px = pw[i*3+0], py = pw[i*3+1], pz = pw[i*3+2];

        float dx0 = px + (R00*t0 + R10*t1 + R20*t2);
        float dy0 = py + (R01*t0 + R11*t1 + R21*t2);
        float dz0 = pz + (R02*t0 + R12*t1 + R22*t2);
        float dn = rsqrtf(dx0*dx0 + dy0*dy0 + dz0*dz0);
        float x = dx0*dn, y = dy0*dn, z = dz0*dn;

        float xx = x*x, yy = y*y, zz = z*z;
        float xy = x*y, yz = y*z, xz = x*z;

        const float* hs = highsh + i*45 + ch;
        float res = C0 * lowsh[i*3+ch];
        res += (-C1*y) * hs[0*3] + (C1*z) * hs[1*3] + (-C1*x) * hs[2*3];
        res += (C2_[0]*xy) * hs[3*3] + (C2_[1]*yz) * hs[4*3]
             + (C2_[2]*(2.0f*zz - xx - yy)) * hs[5*3]
             + (C2_[3]*xz) * hs[6*3] + (C2_[4]*(xx - yy)) * hs[7*3];
        res += (C3_[0]*y*(3.0f*xx - yy)) * hs[8*3]
             + (C3_[1]*xy*z) * hs[9*3]
             + (C3_[2]*y*(4.0f*zz - xx - yy)) * hs[10*3]
             + (C3_[3]*z*(2.0f*zz - 3.0f*xx - 3.0f*yy)) * hs[11*3]
             + (C3_[4]*x*(4.0f*zz - xx - yy)) * hs[12*3]
             + (C3_[5]*z*(xx - yy)) * hs[13*3]
             + (C3_[6]*x*(xx - 3.0f*yy)) * hs[14*3];
        ((float*)&g_col[i])[ch] = fmaxf(res + 0.5f, 0.0f);
    }

    gbar();

    // ---------------- Phase B: scatter into depth order ----------------
    if (gid < n) {
        int r = g_rank[gid];
        float4 d = g_d[gid];
        float2 k = g_k[gid];
        float4 c = g_col[gid];
        s_a[r] = g_a[gid];
        s_b[r] = make_float4(d.x, d.y, c.x, c.y);      // (Cc2, op, colR, colG)
        s_c[r] = make_float4(c.z, d.z, k.x, k.y);      // (colB, thr, kX, kY)
    }

    gbar();

    // ------ Phase C: exact cull (order-preserving) + warp split-K blend + compose --
    {
        // re-zero ranks for the NEXT launch (scatter above already consumed them)
        if (gid < n) g_rank[gid] = 0;

        int tlx = blk & (TILES_X - 1);
        int tly = blk >> 4;

        float xlo = tlx * TILE + 0.5f, xhi = tlx * TILE + (TILE - 0.5f);
        float ylo = tly * TILE + 0.5f, yhi = tly * TILE + (TILE - 0.5f);

        int wid = t >> 5, lid = t & 31;
        unsigned lmask = (1u << lid) - 1u;

        // exact anisotropic cull over the depth-sorted arrays
        int cnt = 0;
        for (int c = 0; c < n; c += BLK4) {
            int i = c + t;
            int pred = 0;
            if (i < n) {
                float4 A = s_a[i];          // u, v, A2, B2
                float4 E = s_c[i];          // colB, thr, kX, kY
                float Cc = s_b[i].x;        // C2
                float A2 = A.z, B2 = A.w;
                // dx = u - px over px in [xlo,xhi]; concave quadratic max over box
                float dxl = A.x - xhi, dxh = A.x - xlo;
                float dyl = A.y - yhi, dyh = A.y - ylo;
                float m;
                if (dxl <= 0.0f && dxh >= 0.0f && dyl <= 0.0f && dyh >= 0.0f) {
                    m = 0.0f;               // interior critical point (global max)
                } else {
                    // 4 edges, clamped-vertex evaluation (exact for concave 1D)
                    float vy0 = fminf(fmaxf(dxl * E.w, dyl), dyh);
                    float f0  = fmaf(fmaf(Cc, vy0, B2 * dxl), vy0, A2 * dxl * dxl);
                    float vy1 = fminf(fmaxf(dxh * E.w, dyl), dyh);
                    float f1  = fmaf(fmaf(Cc, vy1, B2 * dxh), vy1, A2 * dxh * dxh);
                    float vx0 = fminf(fmaxf(dyl * E.z, dxl), dxh);
                    float f2  = fmaf(fmaf(A2, vx0, B2 * dyl), vx0, Cc * dyl * dyl);
                    float vx1 = fminf(fmaxf(dyh * E.z, dxl), dxh);
                    float f3  = fmaf(fmaf(A2, vx1, B2 * dyh), vx1, Cc * dyh * dyh);
                    m = fmaxf(fmaxf(f0, f1), fmaxf(f2, f3));
                }
                pred = (m >= E.y - 1e-3f) ? 1 : 0;   // conservative margin
            }
            unsigned bm = __ballot_sync(0xffffffffu, pred);
            if (lid == 0) sm.c.wcnt[wid] = __popc(bm);
            __syncthreads();
            int orig = (lid < 16) ? sm.c.wcnt[lid] : 0;
            int incl = orig;
            #pragma unroll
            for (int d = 1; d < 16; d <<= 1) {
                int v = __shfl_up_sync(0xffffffffu, incl, d);
                if (lid >= d) incl += v;
            }
            int wbase = __shfl_sync(0xffffffffu, incl, wid)
                      - __shfl_sync(0xffffffffu, orig, wid);
            int tot   = __shfl_sync(0xffffffffu, incl, 15);
            if (pred) sm.c.slist[cnt + wbase + __popc(bm & lmask)] = (unsigned short)i;
            __syncthreads();
            cnt += tot;
        }

        // warp split-K: warp w = (segment q = w>>1, pixel-half h = w&1)
        int q = wid >> 1;
        int h = wid & 1;
        int pix = h * 32 + lid;
        float pxf = tlx * TILE + (pix & 7) + 0.5f;
        float pyf = tly * TILE + (pix >> 3) + 0.5f;

        int L8 = (cnt + 7) >> 3;
        int qbeg = q * L8;
        int qend = min(cnt, qbeg + L8);

        float T = 1.0f, cr = 0.0f, cg = 0.0f, cbl = 0.0f;

        for (int base = 0; base < L8; base += 32) {
            if (__all_sync(0xffffffffu, T < 1e-5f)) break;
            int src = qbeg + base + lid;
            if (src < qend) {
                int idx = sm.c.slist[src];
                sm.c.ca[wid][lid]  = s_a[idx];
                sm.c.cb[wid][lid]  = s_b[idx];
                sm.c.ccb[wid][lid] = s_c[idx].x;
            }
            __syncwarp();
            int m = min(32, qend - (qbeg + base));
            #pragma unroll 4
            for (int k = 0; k < m; k++) {
                float4 A = sm.c.ca[wid][k];
                float4 B = sm.c.cb[wid][k];
                float dx = A.x - pxf;
                float dy = A.y - pyf;
                float pp = A.z * dx * dx;
                pp = fmaf(B.x, dy * dy, pp);
                pp = fmaf(A.w, dx * dy, pp);
                pp = fminf(pp, 0.0f);
                float gw;
                asm("ex2.approx.f32 %0, %1;" : "=f"(gw) : "f"(pp));
                float alpha = fminf(0.99f, B.y * gw);
                alpha = (alpha >= (1.0f / 255.0f)) ? alpha : 0.0f;
                float w = T * alpha;
                cr  = fmaf(w, B.z, cr);
                cg  = fmaf(w, B.w, cg);
                cbl = fmaf(w, sm.c.ccb[wid][k], cbl);
                T = fmaf(-alpha, T, T);
            }
            __syncwarp();
        }

        sm.c.part[q][pix] = make_float4(cr, cg, cbl, T);
        __syncthreads();

        // compose 8 segments front-to-back (threads 0..63)
        if (t < 64) {
            float Tc = 1.0f, rr = 0.0f, gg = 0.0f, bb = 0.0f;
            #pragma unroll
            for (int s = 0; s < 8; s++) {
                float4 P = sm.c.part[s][t];
                rr = fmaf(Tc, P.x, rr);
                gg = fmaf(Tc, P.y, gg);
                bb = fmaf(Tc, P.z, bb);
                Tc *= P.w;
            }
            int pxi = tlx * TILE + (t & 7);
            int pyi = tly * TILE + (t >> 3);
            int o = (pyi * IMG_W + pxi) * 3;
            out[o + 0] = rr;
            out[o + 1] = gg;
            out[o + 2] = bb;
        }
    }
}

extern "C" void kernel_launch(void* const* d_in, const int* in_sizes, int n_in,
                              void* d_out, int out_size) {
    const float* pw     = (const float*)d_in[0];
    const float* lowsh  = (const float*)d_in[1];
    const float* highsh = (const float*)d_in[2];
    const float* rawop  = (const float*)d_in[3];
    const float* sraw   = (const float*)d_in[4];
    const float* rraw   = (const float*)d_in[5];
    const float* Rcw    = (const float*)d_in[6];
    const float* tcw    = (const float*)d_in[7];
    int n = in_sizes[0] / 3;

    fused_kernel<<<GRID4, BLK4>>>(pw, lowsh, highsh, rawop, sraw, rraw, Rcw, tcw,
                                  (float*)d_out, n);
}